// round 9
// baseline (speedup 1.0000x reference)
#include <cuda_runtime.h>
#include <cuda_fp16.h>
#include <cstdint>
#include <cstddef>

#define N_NODES 8192
#define F_DIM   128
#define KC      64
#define KSPLIT  2
#define JSPAN   (N_NODES / KSPLIT)   // 4096
#define CHUNKS  (JSPAN / KC)         // 64
#define M_CTA   128
#define NTHREADS 512

// smem bytes: A[2][128][72]h (stride 144B) = 36864, B[2][128][72]h = 36864
#define A_OFF(b)  ((b) * 18432)
#define B_OFF(b)  (36864 + (b) * 18432)
#define DYN_SMEM  73728

// ---- scratch ----
__device__ float  g_h   [N_NODES * F_DIM];
__device__ __half g_hT  [(size_t)F_DIM * N_NODES];      // h fp16 transposed [f][j]
__device__ float  g_q   [N_NODES];                      // exp(0.8*f1)
__device__ float4 g_jc  [N_NODES];                      // {exp(f2), exp(0.2*f2), W2, 0}
__device__ float  g_part[KSPLIT][N_NODES * F_DIM];      // partial numerators
__device__ float  g_z   [KSPLIT][N_NODES];              // partial z
__device__ float  g_rp  [KSPLIT][N_NODES];              // partial r

// ===================== helpers =====================
__device__ __forceinline__ uint32_t smem_u32(const void* p) {
    uint32_t a;
    asm("{ .reg .u64 t; cvta.to.shared.u64 t, %1; cvt.u32.u64 %0, t; }" : "=r"(a) : "l"(p));
    return a;
}
__device__ __forceinline__ void mma16(float* d, const uint32_t* a, uint32_t b0, uint32_t b1) {
    asm volatile("mma.sync.aligned.m16n8k16.row.col.f32.f16.f16.f32 "
        "{%0,%1,%2,%3}, {%4,%5,%6,%7}, {%8,%9}, {%0,%1,%2,%3};"
        : "+f"(d[0]), "+f"(d[1]), "+f"(d[2]), "+f"(d[3])
        : "r"(a[0]), "r"(a[1]), "r"(a[2]), "r"(a[3]), "r"(b0), "r"(b1));
}
__device__ __forceinline__ void ldsm4(uint32_t* r, uint32_t addr) {
    asm volatile("ldmatrix.sync.aligned.m8n8.x4.shared.b16 {%0,%1,%2,%3}, [%4];"
        : "=r"(r[0]), "=r"(r[1]), "=r"(r[2]), "=r"(r[3]) : "r"(addr));
}
__device__ __forceinline__ void cp16(uint32_t daddr, const void* gsrc) {
    asm volatile("cp.async.cg.shared.global [%0], [%1], 16;"
                 :: "r"(daddr), "l"(gsrc) : "memory");
}

// ===================== Kernel 1: prep =====================
__global__ __launch_bounds__(256) void prep_kernel(const float* __restrict__ x,
                                                   const float* __restrict__ W,
                                                   const float* __restrict__ a,
                                                   const float* __restrict__ W2) {
    int wid = threadIdx.x >> 5, lane = threadIdx.x & 31;
    int i = blockIdx.x * 8 + wid;
    float4 xv = *(const float4*)&x[(size_t)i * F_DIM + lane * 4];
    float4 wv = *(const float4*)&W[(size_t)i * F_DIM + lane * 4];
    float4 h;
    h.x = xv.x * wv.x; h.y = xv.y * wv.y; h.z = xv.z * wv.z; h.w = xv.w * wv.w;
    *(float4*)&g_h[(size_t)i * F_DIM + lane * 4] = h;

    float4 a1 = *(const float4*)&a[lane * 4];
    float4 a2 = *(const float4*)&a[F_DIM + lane * 4];
    float p1 = h.x * a1.x + h.y * a1.y + h.z * a1.z + h.w * a1.w;
    float p2 = h.x * a2.x + h.y * a2.y + h.z * a2.z + h.w * a2.w;
    #pragma unroll
    for (int off = 16; off; off >>= 1) {
        p1 += __shfl_xor_sync(0xffffffffu, p1, off);
        p2 += __shfl_xor_sync(0xffffffffu, p2, off);
    }
    if (lane == 0) {
        g_q[i] = expf(0.8f * p1);
        float4 jc;
        jc.x = expf(p2);
        jc.y = expf(0.2f * p2);
        jc.z = W2[i];
        jc.w = 0.f;
        g_jc[i] = jc;
    }
}

// ===================== Kernel 2: transpose + fp16 convert =====================
__global__ __launch_bounds__(256) void transpose_kernel() {
    __shared__ float t[32][33];
    int j0 = blockIdx.x * 32, f0 = blockIdx.y * 32;
    int tx = threadIdx.x & 31, ty = threadIdx.x >> 5;
    #pragma unroll
    for (int k = 0; k < 4; k++)
        t[ty + k * 8][tx] = g_h[(size_t)(j0 + ty + k * 8) * F_DIM + f0 + tx];
    __syncthreads();
    #pragma unroll
    for (int k = 0; k < 4; k++)
        g_hT[(size_t)(f0 + ty + k * 8) * N_NODES + j0 + tx] = __float2half(t[tx][ty + k * 8]);
}

// ===================== Kernel 3: split-K fp16 mma attention =====================
// grid (64, 2): x = i-block (128 rows), y = j-split (4096 cols). One wave.
// 512 threads / 16 warps; warp tile 32x32: mw = wid&3, nw = wid>>2.
__global__ __launch_bounds__(NTHREADS, 1) void attn_kernel(const int* __restrict__ adj) {
    extern __shared__ char smc[];
    uint32_t sb = smem_u32(smc);

    int tid = threadIdx.x, wid = tid >> 5, lane = tid & 31;
    int i0 = blockIdx.x * M_CTA;
    int split = blockIdx.y;
    int jbase = split * JSPAN;
    int mw = wid & 3, nw = wid >> 2;

    // ldmatrix per-lane offsets (row stride 144B)
    uint32_t offA = (uint32_t)(lane & 15) * 144u + (uint32_t)(lane & 16);
    uint32_t offB = ((uint32_t)(lane & 7) + ((uint32_t)(lane & 16) >> 1)) * 144u
                  + ((uint32_t)(lane & 8) << 1);

    // build state: warp owns rows wid*8..+7; lane owns j pair (2*lane, 2*lane+1)
    float pi[8], zp[8], rp[8];
    const int* ap = adj + (size_t)(i0 + wid * 8) * N_NODES + jbase + 2 * lane;
    #pragma unroll
    for (int k = 0; k < 8; k++) {
        pi[k] = g_q[i0 + wid * 8 + k];
        zp[k] = 0.f; rp[k] = 0.f;
    }

    float acc[2][4][4];
    #pragma unroll
    for (int mt = 0; mt < 2; mt++)
        #pragma unroll
        for (int nt = 0; nt < 4; nt++)
            acc[mt][nt][0] = acc[mt][nt][1] = acc[mt][nt][2] = acc[mt][nt][3] = 0.f;

    // ---- prologue: chunk-0 scalars + B(0) in flight ----
    int2 av[8];
    float4 jcA = g_jc[jbase + 2 * lane];
    float4 jcB = g_jc[jbase + 2 * lane + 1];
    #pragma unroll
    for (int k = 0; k < 8; k++) av[k] = __ldcs((const int2*)(ap + (size_t)k * N_NODES));
    #pragma unroll
    for (int p = 0; p < 2; p++) {
        int idx = tid + p * NTHREADS;
        int col = idx >> 3, seg = idx & 7;
        cp16(sb + B_OFF(0) + col * 144 + seg * 16,
             &g_hT[(size_t)col * N_NODES + jbase + seg * 8]);
    }
    asm volatile("cp.async.commit_group;" ::: "memory");

    for (int c = 0; c < CHUNKS; c++) {
        int bu = c & 1;
        // ---- build A tile (fp16 w' pairs) + z/r ----
        #pragma unroll
        for (int k = 0; k < 8; k++) {
            float w0 = av[k].x ? fmaxf(pi[k] * jcA.x, jcA.y) : 0.f;
            float w1 = av[k].y ? fmaxf(pi[k] * jcB.x, jcB.y) : 0.f;
            __half2 hw = __floats2half2_rn(w0, w1);
            *(__half2*)(smc + A_OFF(bu) + (wid * 8 + k) * 144 + lane * 4) = hw;
            zp[k] += __low2float(hw) + __high2float(hw);
            rp[k] += (av[k].x ? jcA.z : 0.f) + (av[k].y ? jcB.z : 0.f);
        }
        // ---- prefetch scalars for chunk c+1 ----
        if (c + 1 < CHUNKS) {
            jcA = g_jc[jbase + (c + 1) * KC + 2 * lane];
            jcB = g_jc[jbase + (c + 1) * KC + 2 * lane + 1];
            const int* ap2 = ap + (c + 1) * KC;
            #pragma unroll
            for (int k = 0; k < 8; k++)
                av[k] = __ldcs((const int2*)(ap2 + (size_t)k * N_NODES));
        }
        asm volatile("cp.async.wait_group 0;" ::: "memory");   // B(c) landed
        __syncthreads();                                        // A(c) visible
        // ---- issue B(c+1) into other buffer (overlaps mma) ----
        if (c + 1 < CHUNKS) {
            #pragma unroll
            for (int p = 0; p < 2; p++) {
                int idx = tid + p * NTHREADS;
                int col = idx >> 3, seg = idx & 7;
                cp16(sb + B_OFF(bu ^ 1) + col * 144 + seg * 16,
                     &g_hT[(size_t)col * N_NODES + jbase + (c + 1) * KC + seg * 8]);
            }
            asm volatile("cp.async.commit_group;" ::: "memory");
        }
        // ---- mma: 4 k16 steps, warp tile 32x32, LDSM fragments ----
        uint32_t Ab = sb + A_OFF(bu) + (mw * 32) * 144 + offA;
        uint32_t Bb = sb + B_OFF(bu) + (nw * 32) * 144 + offB;
        #pragma unroll
        for (int s = 0; s < 4; s++) {
            uint32_t af[2][4], bq0[4], bq1[4];
            ldsm4(af[0], Ab + s * 32);
            ldsm4(af[1], Ab + 16 * 144 + s * 32);
            ldsm4(bq0, Bb + s * 32);
            ldsm4(bq1, Bb + 16 * 144 + s * 32);
            #pragma unroll
            for (int mt = 0; mt < 2; mt++) {
                mma16(acc[mt][0], af[mt], bq0[0], bq0[1]);
                mma16(acc[mt][1], af[mt], bq0[2], bq0[3]);
                mma16(acc[mt][2], af[mt], bq1[0], bq1[1]);
                mma16(acc[mt][3], af[mt], bq1[2], bq1[3]);
            }
        }
    }

    // ---- reduce z, r across lanes; write split partials ----
    #pragma unroll
    for (int k = 0; k < 8; k++) {
        float z = zp[k], r = rp[k];
        #pragma unroll
        for (int off = 16; off; off >>= 1) {
            z += __shfl_xor_sync(0xffffffffu, z, off);
            r += __shfl_xor_sync(0xffffffffu, r, off);
        }
        zp[k] = z; rp[k] = r;
    }
    if (lane == 0) {
        #pragma unroll
        for (int k = 0; k < 8; k++) {
            g_z [split][i0 + wid * 8 + k] = zp[k];
            g_rp[split][i0 + wid * 8 + k] = rp[k];
        }
    }

    // ---- write partial numerators ----
    int gl = lane >> 2, ql = lane & 3;
    float* part = g_part[split];
    #pragma unroll
    for (int mt = 0; mt < 2; mt++) {
        int r0 = mw * 32 + mt * 16 + gl;
        #pragma unroll
        for (int nt = 0; nt < 4; nt++) {
            int col = nw * 32 + nt * 8 + ql * 2;
            *(float2*)&part[(size_t)(i0 + r0) * F_DIM + col] =
                make_float2(acc[mt][nt][0], acc[mt][nt][1]);
            *(float2*)&part[(size_t)(i0 + r0 + 8) * F_DIM + col] =
                make_float2(acc[mt][nt][2], acc[mt][nt][3]);
        }
    }
}

// ===================== Kernel 4: combine partials =====================
__global__ __launch_bounds__(256) void combine_kernel(float* __restrict__ hp) {
    int idx = blockIdx.x * 256 + threadIdx.x;   // float4 index
    int i = idx >> 5;
    float z = g_z[0][i] + g_z[1][i];
    float inv = 1.0f / z;
    float4 s0 = ((const float4*)g_part[0])[idx];
    float4 s1 = ((const float4*)g_part[1])[idx];
    float4 o;
    o.x = (s0.x + s1.x) * inv;
    o.y = (s0.y + s1.y) * inv;
    o.z = (s0.z + s1.z) * inv;
    o.w = (s0.w + s1.w) * inv;
    ((float4*)hp)[idx] = o;
}

// ===================== Kernel 5: out = elu(r^T @ x) =====================
__global__ void out_kernel(const float* __restrict__ x, float* __restrict__ out) {
    int f = blockIdx.x;
    float p = 0.f;
    for (int i = threadIdx.x; i < N_NODES; i += 256) {
        float r = g_rp[0][i] + g_rp[1][i];
        p += r * x[(size_t)i * F_DIM + f];
    }
    #pragma unroll
    for (int off = 16; off; off >>= 1)
        p += __shfl_xor_sync(0xffffffffu, p, off);
    __shared__ float s[8];
    int lane = threadIdx.x & 31, wid = threadIdx.x >> 5;
    if (lane == 0) s[wid] = p;
    __syncthreads();
    if (threadIdx.x == 0) {
        float v = 0.f;
        #pragma unroll
        for (int k = 0; k < 8; k++) v += s[k];
        out[f] = (v > 0.f) ? v : (expf(v) - 1.0f);
    }
}

// ===========================================================================
extern "C" void kernel_launch(void* const* d_in, const int* in_sizes, int n_in,
                              void* d_out, int out_size) {
    const float* x   = (const float*)d_in[0];
    const int*   adj = (const int*)  d_in[1];
    const float* W   = (const float*)d_in[2];
    const float* a   = (const float*)d_in[3];
    const float* W2  = (const float*)d_in[4];
    float* out = (float*)d_out;   // [0:128) elu output, [128:) h_prime

    cudaFuncSetAttribute(attn_kernel, cudaFuncAttributeMaxDynamicSharedMemorySize, DYN_SMEM);

    prep_kernel<<<N_NODES / 8, 256>>>(x, W, a, W2);
    transpose_kernel<<<dim3(N_NODES / 32, F_DIM / 32), 256>>>();
    attn_kernel<<<dim3(N_NODES / M_CTA, KSPLIT), NTHREADS, DYN_SMEM>>>(adj);
    combine_kernel<<<(N_NODES * F_DIM / 4) / 256, 256>>>(out + F_DIM);
    out_kernel<<<F_DIM, 256>>>(x, out);
}

// round 10
// speedup vs baseline: 1.0683x; 1.0683x over previous
#include <cuda_runtime.h>
#include <cuda_fp16.h>
#include <cstdint>
#include <cstddef>

#define N_NODES 8192
#define F_DIM   128
#define KC      64
#define KSPLIT  2
#define JSPAN   (N_NODES / KSPLIT)   // 4096
#define CHUNKS  (JSPAN / KC)         // 64
#define M_CTA   64

// smem bytes: A[2][64][72]h (stride 144B) = 18432, B[3][128][72]h = 55296
#define A_OFF(b)  ((b) * 9216)
#define B_OFF(b)  (18432 + (b) * 18432)
#define DYN_SMEM  73728

// ---- scratch ----
__device__ float  g_h   [N_NODES * F_DIM];
__device__ __half g_hT  [(size_t)F_DIM * N_NODES];      // h fp16 transposed [f][j]
__device__ float  g_q   [N_NODES];                      // exp(0.8*f1)
__device__ float4 g_jc  [N_NODES];                      // {exp(f2), exp(0.2*f2), W2, 0}
__device__ float  g_part[KSPLIT][N_NODES * F_DIM];      // partial numerators
__device__ float  g_z   [KSPLIT][N_NODES];              // partial z
__device__ float  g_rp  [KSPLIT][N_NODES];              // partial r

// ===================== helpers =====================
__device__ __forceinline__ uint32_t smem_u32(const void* p) {
    uint32_t a;
    asm("{ .reg .u64 t; cvta.to.shared.u64 t, %1; cvt.u32.u64 %0, t; }" : "=r"(a) : "l"(p));
    return a;
}
__device__ __forceinline__ void mma16(float* d, const uint32_t* a, uint32_t b0, uint32_t b1) {
    asm volatile("mma.sync.aligned.m16n8k16.row.col.f32.f16.f16.f32 "
        "{%0,%1,%2,%3}, {%4,%5,%6,%7}, {%8,%9}, {%0,%1,%2,%3};"
        : "+f"(d[0]), "+f"(d[1]), "+f"(d[2]), "+f"(d[3])
        : "r"(a[0]), "r"(a[1]), "r"(a[2]), "r"(a[3]), "r"(b0), "r"(b1));
}
__device__ __forceinline__ void ldsm4(uint32_t* r, uint32_t addr) {
    asm volatile("ldmatrix.sync.aligned.m8n8.x4.shared.b16 {%0,%1,%2,%3}, [%4];"
        : "=r"(r[0]), "=r"(r[1]), "=r"(r[2]), "=r"(r[3]) : "r"(addr));
}
__device__ __forceinline__ void cp16(uint32_t daddr, const void* gsrc) {
    asm volatile("cp.async.cg.shared.global [%0], [%1], 16;"
                 :: "r"(daddr), "l"(gsrc) : "memory");
}

// ===================== Kernel 1: prep =====================
__global__ __launch_bounds__(256) void prep_kernel(const float* __restrict__ x,
                                                   const float* __restrict__ W,
                                                   const float* __restrict__ a,
                                                   const float* __restrict__ W2) {
    int wid = threadIdx.x >> 5, lane = threadIdx.x & 31;
    int i = blockIdx.x * 8 + wid;
    float4 xv = *(const float4*)&x[(size_t)i * F_DIM + lane * 4];
    float4 wv = *(const float4*)&W[(size_t)i * F_DIM + lane * 4];
    float4 h;
    h.x = xv.x * wv.x; h.y = xv.y * wv.y; h.z = xv.z * wv.z; h.w = xv.w * wv.w;
    *(float4*)&g_h[(size_t)i * F_DIM + lane * 4] = h;

    float4 a1 = *(const float4*)&a[lane * 4];
    float4 a2 = *(const float4*)&a[F_DIM + lane * 4];
    float p1 = h.x * a1.x + h.y * a1.y + h.z * a1.z + h.w * a1.w;
    float p2 = h.x * a2.x + h.y * a2.y + h.z * a2.z + h.w * a2.w;
    #pragma unroll
    for (int off = 16; off; off >>= 1) {
        p1 += __shfl_xor_sync(0xffffffffu, p1, off);
        p2 += __shfl_xor_sync(0xffffffffu, p2, off);
    }
    if (lane == 0) {
        g_q[i] = expf(0.8f * p1);
        float4 jc;
        jc.x = expf(p2);
        jc.y = expf(0.2f * p2);
        jc.z = W2[i];
        jc.w = 0.f;
        g_jc[i] = jc;
    }
}

// ===================== Kernel 2: transpose + fp16 convert =====================
__global__ __launch_bounds__(256) void transpose_kernel() {
    __shared__ float t[32][33];
    int j0 = blockIdx.x * 32, f0 = blockIdx.y * 32;
    int tx = threadIdx.x & 31, ty = threadIdx.x >> 5;
    #pragma unroll
    for (int k = 0; k < 4; k++)
        t[ty + k * 8][tx] = g_h[(size_t)(j0 + ty + k * 8) * F_DIM + f0 + tx];
    __syncthreads();
    #pragma unroll
    for (int k = 0; k < 4; k++)
        g_hT[(size_t)(f0 + ty + k * 8) * N_NODES + j0 + tx] = __float2half(t[tx][ty + k * 8]);
}

// ===================== Kernel 3: split-K fp16 mma attention =====================
// grid (128, 2): x = i-block (64 rows), y = j-split (4096 cols). 256 CTAs,
// 2 CTAs/SM -> single wave. 256 threads / 8 warps; warp tile 32x32.
__global__ __launch_bounds__(256, 2) void attn_kernel(const int* __restrict__ adj) {
    extern __shared__ char smc[];
    uint32_t sb = smem_u32(smc);

    int tid = threadIdx.x, wid = tid >> 5, lane = tid & 31;
    int i0 = blockIdx.x * M_CTA;
    int split = blockIdx.y;
    int jbase = split * JSPAN;
    int mw = wid & 1, nw = wid >> 1;

    // ldmatrix per-lane offsets (row stride 144B)
    uint32_t offA = (uint32_t)(lane & 15) * 144u + (uint32_t)(lane & 16);
    uint32_t offB = ((uint32_t)(lane & 7) + ((uint32_t)(lane & 16) >> 1)) * 144u
                  + ((uint32_t)(lane & 8) << 1);

    // build state: warp owns rows wid*8..+7; lane owns j pair (2*lane, 2*lane+1)
    float pi[8], zp[8], rp[8];
    const int* ap = adj + (size_t)(i0 + wid * 8) * N_NODES + jbase + 2 * lane;
    #pragma unroll
    for (int k = 0; k < 8; k++) {
        pi[k] = g_q[i0 + wid * 8 + k];
        zp[k] = 0.f; rp[k] = 0.f;
    }

    float acc[2][4][4];
    #pragma unroll
    for (int mt = 0; mt < 2; mt++)
        #pragma unroll
        for (int nt = 0; nt < 4; nt++)
            acc[mt][nt][0] = acc[mt][nt][1] = acc[mt][nt][2] = acc[mt][nt][3] = 0.f;

    // ---- prologue: chunk-0 scalars; B(0), B(1) in flight ----
    int2 av[8];
    float4 jcA = g_jc[jbase + 2 * lane];
    float4 jcB = g_jc[jbase + 2 * lane + 1];
    #pragma unroll
    for (int k = 0; k < 8; k++) av[k] = __ldcs((const int2*)(ap + (size_t)k * N_NODES));
    #pragma unroll
    for (int pre = 0; pre < 2; pre++) {
        #pragma unroll
        for (int p = 0; p < 4; p++) {
            int idx = tid + p * 256;
            int col = idx >> 3, seg = idx & 7;
            cp16(sb + B_OFF(pre) + col * 144 + seg * 16,
                 &g_hT[(size_t)col * N_NODES + jbase + pre * KC + seg * 8]);
        }
        asm volatile("cp.async.commit_group;" ::: "memory");
    }

    for (int c = 0; c < CHUNKS; c++) {
        int ba = c & 1;
        int bb = c % 3;
        // ---- build A tile (fp16 w' pairs) + z/r ----
        #pragma unroll
        for (int k = 0; k < 8; k++) {
            float w0 = av[k].x ? fmaxf(pi[k] * jcA.x, jcA.y) : 0.f;
            float w1 = av[k].y ? fmaxf(pi[k] * jcB.x, jcB.y) : 0.f;
            __half2 hw = __floats2half2_rn(w0, w1);
            *(__half2*)(smc + A_OFF(ba) + (wid * 8 + k) * 144 + lane * 4) = hw;
            zp[k] += __low2float(hw) + __high2float(hw);
            rp[k] += (av[k].x ? jcA.z : 0.f) + (av[k].y ? jcB.z : 0.f);
        }
        // ---- prefetch scalars for chunk c+1 ----
        if (c + 1 < CHUNKS) {
            jcA = g_jc[jbase + (c + 1) * KC + 2 * lane];
            jcB = g_jc[jbase + (c + 1) * KC + 2 * lane + 1];
            const int* ap2 = ap + (c + 1) * KC;
            #pragma unroll
            for (int k = 0; k < 8; k++)
                av[k] = __ldcs((const int2*)(ap2 + (size_t)k * N_NODES));
        }
        asm volatile("cp.async.wait_group 1;" ::: "memory");   // B(c) landed, B(c+1) may fly
        __syncthreads();                                        // A(c) visible
        // ---- issue B(c+2) (always commit to keep group count in step) ----
        if (c + 2 < CHUNKS) {
            #pragma unroll
            for (int p = 0; p < 4; p++) {
                int idx = tid + p * 256;
                int col = idx >> 3, seg = idx & 7;
                cp16(sb + B_OFF((c + 2) % 3) + col * 144 + seg * 16,
                     &g_hT[(size_t)col * N_NODES + jbase + (c + 2) * KC + seg * 8]);
            }
        }
        asm volatile("cp.async.commit_group;" ::: "memory");
        // ---- mma: 4 k16 steps, warp tile 32x32, LDSM fragments ----
        uint32_t Ab = sb + A_OFF(ba) + (mw * 32) * 144 + offA;
        uint32_t Bb = sb + B_OFF(bb) + (nw * 32) * 144 + offB;
        #pragma unroll
        for (int s = 0; s < 4; s++) {
            uint32_t af[2][4], bq0[4], bq1[4];
            ldsm4(af[0], Ab + s * 32);
            ldsm4(af[1], Ab + 16 * 144 + s * 32);
            ldsm4(bq0, Bb + s * 32);
            ldsm4(bq1, Bb + 16 * 144 + s * 32);
            #pragma unroll
            for (int mt = 0; mt < 2; mt++) {
                mma16(acc[mt][0], af[mt], bq0[0], bq0[1]);
                mma16(acc[mt][1], af[mt], bq0[2], bq0[3]);
                mma16(acc[mt][2], af[mt], bq1[0], bq1[1]);
                mma16(acc[mt][3], af[mt], bq1[2], bq1[3]);
            }
        }
    }

    // ---- reduce z, r across lanes; write split partials ----
    #pragma unroll
    for (int k = 0; k < 8; k++) {
        float z = zp[k], r = rp[k];
        #pragma unroll
        for (int off = 16; off; off >>= 1) {
            z += __shfl_xor_sync(0xffffffffu, z, off);
            r += __shfl_xor_sync(0xffffffffu, r, off);
        }
        zp[k] = z; rp[k] = r;
    }
    if (lane == 0) {
        #pragma unroll
        for (int k = 0; k < 8; k++) {
            g_z [split][i0 + wid * 8 + k] = zp[k];
            g_rp[split][i0 + wid * 8 + k] = rp[k];
        }
    }

    // ---- write partial numerators ----
    int gl = lane >> 2, ql = lane & 3;
    float* part = g_part[split];
    #pragma unroll
    for (int mt = 0; mt < 2; mt++) {
        int r0 = mw * 32 + mt * 16 + gl;
        #pragma unroll
        for (int nt = 0; nt < 4; nt++) {
            int col = nw * 32 + nt * 8 + ql * 2;
            *(float2*)&part[(size_t)(i0 + r0) * F_DIM + col] =
                make_float2(acc[mt][nt][0], acc[mt][nt][1]);
            *(float2*)&part[(size_t)(i0 + r0 + 8) * F_DIM + col] =
                make_float2(acc[mt][nt][2], acc[mt][nt][3]);
        }
    }
}

// ===================== Kernel 4: combine partials =====================
__global__ __launch_bounds__(256) void combine_kernel(float* __restrict__ hp) {
    int idx = blockIdx.x * 256 + threadIdx.x;   // float4 index
    int i = idx >> 5;
    float z = g_z[0][i] + g_z[1][i];
    float inv = 1.0f / z;
    float4 s0 = ((const float4*)g_part[0])[idx];
    float4 s1 = ((const float4*)g_part[1])[idx];
    float4 o;
    o.x = (s0.x + s1.x) * inv;
    o.y = (s0.y + s1.y) * inv;
    o.z = (s0.z + s1.z) * inv;
    o.w = (s0.w + s1.w) * inv;
    ((float4*)hp)[idx] = o;
}

// ===================== Kernel 5: out = elu(r^T @ x) =====================
__global__ void out_kernel(const float* __restrict__ x, float* __restrict__ out) {
    int f = blockIdx.x;
    float p = 0.f;
    for (int i = threadIdx.x; i < N_NODES; i += 256) {
        float r = g_rp[0][i] + g_rp[1][i];
        p += r * x[(size_t)i * F_DIM + f];
    }
    #pragma unroll
    for (int off = 16; off; off >>= 1)
        p += __shfl_xor_sync(0xffffffffu, p, off);
    __shared__ float s[8];
    int lane = threadIdx.x & 31, wid = threadIdx.x >> 5;
    if (lane == 0) s[wid] = p;
    __syncthreads();
    if (threadIdx.x == 0) {
        float v = 0.f;
        #pragma unroll
        for (int k = 0; k < 8; k++) v += s[k];
        out[f] = (v > 0.f) ? v : (expf(v) - 1.0f);
    }
}

// ===========================================================================
extern "C" void kernel_launch(void* const* d_in, const int* in_sizes, int n_in,
                              void* d_out, int out_size) {
    const float* x   = (const float*)d_in[0];
    const int*   adj = (const int*)  d_in[1];
    const float* W   = (const float*)d_in[2];
    const float* a   = (const float*)d_in[3];
    const float* W2  = (const float*)d_in[4];
    float* out = (float*)d_out;   // [0:128) elu output, [128:) h_prime

    cudaFuncSetAttribute(attn_kernel, cudaFuncAttributeMaxDynamicSharedMemorySize, DYN_SMEM);

    prep_kernel<<<N_NODES / 8, 256>>>(x, W, a, W2);
    transpose_kernel<<<dim3(N_NODES / 32, F_DIM / 32), 256>>>();
    attn_kernel<<<dim3(N_NODES / M_CTA, KSPLIT), 256, DYN_SMEM>>>(adj);
    combine_kernel<<<(N_NODES * F_DIM / 4) / 256, 256>>>(out + F_DIM);
    out_kernel<<<F_DIM, 256>>>(x, out);
}